// round 12
// baseline (speedup 1.0000x reference)
#include <cuda_runtime.h>
#include <cuda_bf16.h>
#include <cstdint>

// Capsule routing, factorized. Fused per-pass tf32-MMA routing kernel
// (blog -> smem softmax -> sgemm), split-partial reduction kernel, lean caps.
// u (32,1024,256) f32; W (256,2048) f32; out (32,32,64) f32.

#define BB 32
#define II 1024
#define CC 256
#define NN 32
#define DD 64
#define ND 2048
#define ICH 16   // i-chunks of 64 -> # of S partials

typedef unsigned int uint;

__device__ float g_part[BB * 8 * CC];            // colsum partials
__device__ float g_V[BB * NN * CC];              // V[b][n][c]
__device__ float g_Spart[ICH * BB * NN * CC];    // S partials [ich][b][n][c]
__device__ float g_S[BB * NN * CC];              // reduced S

__device__ __forceinline__ uint tf32c(float f) {
    uint r; asm("cvt.rna.tf32.f32 %0, %1;" : "=r"(r) : "f"(f)); return r;
}
__device__ __forceinline__ void mma_tf32(float* d, uint a0, uint a1, uint a2, uint a3,
                                         uint b0, uint b1) {
    asm("mma.sync.aligned.m16n8k8.row.col.f32.tf32.tf32.f32 "
        "{%0,%1,%2,%3},{%4,%5,%6,%7},{%8,%9},{%0,%1,%2,%3};"
        : "+f"(d[0]), "+f"(d[1]), "+f"(d[2]), "+f"(d[3])
        : "r"(a0), "r"(a1), "r"(a2), "r"(a3), "r"(b0), "r"(b1));
}
__device__ __forceinline__ uint4 cvt4(float4 v) {
    return make_uint4(tf32c(v.x), tf32c(v.y), tf32c(v.z), tf32c(v.w));
}

// ---- colsum partials ----------------------------------------------------
__global__ void k_colsum_part(const float* __restrict__ u) {
    int q = blockIdx.x, b = blockIdx.y, c = threadIdx.x;
    const float* p = u + (size_t)b * II * CC + (size_t)q * 128 * CC + c;
    float s = 0.f;
#pragma unroll 8
    for (int i = 0; i < 128; i++) s += p[(size_t)i * CC];
    g_part[(b * 8 + q) * CC + c] = s;
}

// ---- fused routing pass (unchanged from R10) ----------------------------
#define FSM ((96 * 260 + 64 * 36) * 4)
__global__ __launch_bounds__(256) void k_fused(const float* __restrict__ u) {
    extern __shared__ uint smraw[];
    uint (*sU)[260] = (uint(*)[260])smraw;                    // tf32 u [64i][256c]
    uint (*sV)[260] = (uint(*)[260])(smraw + 64 * 260);       // tf32 V [32n][256c]
    float (*sCf)[36] = (float(*)[36])(smraw + 96 * 260);      // logits/coef [64i][32n]

    int ich = blockIdx.x, b = blockIdx.y;
    int i0 = ich * 64;
    int t = threadIdx.x, lane = t & 31, w = t >> 5;
    int g4 = lane >> 2, j4 = lane & 3;

#pragma unroll
    for (int it = 0; it < 8; it++) {
        int idx = it * 256 + t, row = idx >> 6, c4 = idx & 63;
        float4 v = *(const float4*)(g_V + ((size_t)b * NN + row) * CC + c4 * 4);
        *(uint4*)&sV[row][c4 * 4] = cvt4(v);
    }
#pragma unroll
    for (int it = 0; it < 16; it++) {
        int idx = it * 256 + t, row = idx >> 6, c4 = idx & 63;
        float4 v = *(const float4*)(u + ((size_t)b * II + i0 + row) * CC + c4 * 4);
        *(uint4*)&sU[row][c4 * 4] = cvt4(v);
    }
    __syncthreads();

    {   // phase 1: logits[64i x 32n]
        int mt1 = w >> 1, nb = (w & 1) * 2;
        float acc1[2][4] = {};
#pragma unroll 8
        for (int ks = 0; ks < 32; ks++) {
            int k0 = ks * 8;
            uint a0 = sU[mt1 * 16 + g4][k0 + j4];
            uint a1 = sU[mt1 * 16 + g4 + 8][k0 + j4];
            uint a2 = sU[mt1 * 16 + g4][k0 + j4 + 4];
            uint a3 = sU[mt1 * 16 + g4 + 8][k0 + j4 + 4];
#pragma unroll
            for (int ntl = 0; ntl < 2; ntl++) {
                int nt = nb + ntl;
                uint b0 = sV[nt * 8 + g4][k0 + j4];
                uint b1 = sV[nt * 8 + g4][k0 + j4 + 4];
                mma_tf32(acc1[ntl], a0, a1, a2, a3, b0, b1);
            }
        }
#pragma unroll
        for (int ntl = 0; ntl < 2; ntl++) {
            int nt = nb + ntl, ncol = nt * 8 + 2 * j4;
            *(float2*)&sCf[mt1 * 16 + g4][ncol] =
                make_float2(acc1[ntl][0], acc1[ntl][1]);
            *(float2*)&sCf[mt1 * 16 + g4 + 8][ncol] =
                make_float2(acc1[ntl][2], acc1[ntl][3]);
        }
    }
    __syncthreads();

    if (t < 64) {   // softmax over n
        float vv[NN];
        float m = -1e30f;
#pragma unroll
        for (int n = 0; n < NN; n++) { vv[n] = sCf[t][n]; m = fmaxf(m, vv[n]); }
        float s = 0.f;
#pragma unroll
        for (int n = 0; n < NN; n++) { vv[n] = __expf(vv[n] - m); s += vv[n]; }
        float inv = 1.0f / s;
#pragma unroll
        for (int n = 0; n < NN; n++) sCf[t][n] = vv[n] * inv;
    }
    __syncthreads();

    {   // phase 2: Spart = coef^T @ U_chunk
        float acc2[2][4][4] = {};
#pragma unroll
        for (int ks = 0; ks < 8; ks++) {
            int k0 = ks * 8;
            uint a[2][4];
#pragma unroll
            for (int mt = 0; mt < 2; mt++) {
                a[mt][0] = tf32c(sCf[k0 + j4][mt * 16 + g4]);
                a[mt][1] = tf32c(sCf[k0 + j4][mt * 16 + g4 + 8]);
                a[mt][2] = tf32c(sCf[k0 + j4 + 4][mt * 16 + g4]);
                a[mt][3] = tf32c(sCf[k0 + j4 + 4][mt * 16 + g4 + 8]);
            }
#pragma unroll
            for (int ct = 0; ct < 4; ct++) {
                int c = w * 32 + ct * 8 + g4;
                uint b0 = sU[k0 + j4][c];
                uint b1 = sU[k0 + j4 + 4][c];
#pragma unroll
                for (int mt = 0; mt < 2; mt++)
                    mma_tf32(acc2[mt][ct], a[mt][0], a[mt][1], a[mt][2], a[mt][3],
                             b0, b1);
            }
        }
        float* sp = g_Spart + ((size_t)ich * BB + b) * NN * CC;
#pragma unroll
        for (int mt = 0; mt < 2; mt++)
#pragma unroll
            for (int ct = 0; ct < 4; ct++) {
                int cpos = w * 32 + ct * 8 + 2 * j4;
                int n0 = mt * 16 + g4;
                *(float2*)(sp + (size_t)n0 * CC + cpos) =
                    make_float2(acc2[mt][ct][0], acc2[mt][ct][1]);
                *(float2*)(sp + (size_t)(n0 + 8) * CC + cpos) =
                    make_float2(acc2[mt][ct][2], acc2[mt][ct][3]);
            }
    }
}

// ---- k_sum: g_S = sum over ICH partials ---------------------------------
// 65536 float4 elements; grid 256 x 256, one float4/thread, 16-deep MLP.
__global__ __launch_bounds__(256) void k_sum() {
    int idx = blockIdx.x * 256 + threadIdx.x;
    const float4* base = (const float4*)g_Spart;
    float4 a = base[idx];
#pragma unroll
    for (int q = 1; q < ICH; q++) {
        float4 v = base[(size_t)q * (BB * NN * CC / 4) + idx];
        a.x += v.x; a.y += v.y; a.z += v.z; a.w += v.w;
    }
    ((float4*)g_S)[idx] = a;
}

// ---- caps: out = squash(S @ W_n), V = out @ W_n^T -----------------------
#define CAPS_BL 8
#define CAPS_SM ((256 * 65 + CAPS_BL * 256 + CAPS_BL * 68) * 4)
__global__ __launch_bounds__(256) void k_caps(const float* __restrict__ W,
                                              int mode, float* __restrict__ dout) {
    extern __shared__ float sm[];
    float* sW = sm;                      // [256][65]
    float* sS = sm + 256 * 65;           // [8][256]
    float* sO = sS + CAPS_BL * 256;      // [8][68]
    int n = blockIdx.x, bg = blockIdx.y;
    int t = threadIdx.x, lane = t & 31, w = t >> 5;

#pragma unroll
    for (int r = 0; r < 32; r++) {
        int c = w + 8 * r;
        const float* wp = W + (size_t)c * ND + n * DD;
        sW[c * 65 + lane] = wp[lane];
        sW[c * 65 + lane + 32] = wp[lane + 32];
    }
    if (mode == 0) {
#pragma unroll
        for (int bl = 0; bl < CAPS_BL; bl++) {
            int b = bg * CAPS_BL + bl;
            float s = 0.f;
#pragma unroll 4
            for (int q = 0; q < 8; q++) s += g_part[(b * 8 + q) * CC + t];
            sS[bl * CC + t] = s * (1.0f / 32.0f);
        }
    } else {
#pragma unroll
        for (int bl = 0; bl < CAPS_BL; bl++) {
            int b = bg * CAPS_BL + bl;
            sS[bl * CC + t] = g_S[((size_t)b * NN + n) * CC + t];
        }
    }
    __syncthreads();

    // phase A: O[w][d] = sum_c S[w][c] W[c][d]   (warp w -> b-row w)
    float a0 = 0.f, a1 = 0.f;
#pragma unroll 8
    for (int k = 0; k < CC; k += 4) {
        float4 s4 = *(const float4*)&sS[w * CC + k];
        a0 += s4.x * sW[(k + 0) * 65 + lane] + s4.y * sW[(k + 1) * 65 + lane]
            + s4.z * sW[(k + 2) * 65 + lane] + s4.w * sW[(k + 3) * 65 + lane];
        a1 += s4.x * sW[(k + 0) * 65 + lane + 32] + s4.y * sW[(k + 1) * 65 + lane + 32]
            + s4.z * sW[(k + 2) * 65 + lane + 32] + s4.w * sW[(k + 3) * 65 + lane + 32];
    }
    float sq = a0 * a0 + a1 * a1;
#pragma unroll
    for (int off = 16; off; off >>= 1) sq += __shfl_xor_sync(0xffffffffu, sq, off);
    float f = rsqrtf(sq + 1e-7f);
    a0 *= f; a1 *= f;
    sO[w * 68 + lane] = a0; sO[w * 68 + lane + 32] = a1;
    if (mode == 2) {
        int b = bg * CAPS_BL + w;
        dout[(size_t)(b * NN + n) * DD + lane] = a0;
        dout[(size_t)(b * NN + n) * DD + lane + 32] = a1;
        return;
    }
    __syncthreads();

    // phase B: V[w][c] = sum_d O[w][d] W[c][d]
    float accB[8] = {};
#pragma unroll 8
    for (int k = 0; k < DD; k++) {
        float a = sO[w * 68 + k];
#pragma unroll
        for (int q = 0; q < 8; q++) accB[q] += a * sW[(lane + 32 * q) * 65 + k];
    }
    int b = bg * CAPS_BL + w;
#pragma unroll
    for (int q = 0; q < 8; q++)
        g_V[(size_t)(b * NN + n) * CC + lane + 32 * q] = accB[q];
}

// ---------------------------------------------------------------------------
extern "C" void kernel_launch(void* const* d_in, const int* in_sizes, int n_in,
                              void* d_out, int out_size) {
    const float* u = (const float*)d_in[0];
    const float* W = (const float*)d_in[1];
    if (n_in >= 2 && in_sizes[0] == CC * ND) {
        u = (const float*)d_in[1];
        W = (const float*)d_in[0];
    }
    float* out = (float*)d_out;

    cudaFuncSetAttribute(k_caps, cudaFuncAttributeMaxDynamicSharedMemorySize, CAPS_SM);
    cudaFuncSetAttribute(k_fused, cudaFuncAttributeMaxDynamicSharedMemorySize, FSM);

    k_colsum_part<<<dim3(8, BB), 256>>>(u);
    k_caps<<<dim3(NN, BB / CAPS_BL), 256, CAPS_SM>>>(W, 0, nullptr);

    for (int pass = 0; pass < 2; pass++) {
        k_fused<<<dim3(ICH, BB), 256, FSM>>>(u);
        k_sum<<<BB * NN * CC / 4 / 256, 256>>>();
        k_caps<<<dim3(NN, BB / CAPS_BL), 256, CAPS_SM>>>(W, pass == 0 ? 1 : 2,
                                                          pass == 0 ? nullptr : out);
    }
}